// round 13
// baseline (speedup 1.0000x reference)
#include <cuda_runtime.h>
#include <string.h>

typedef unsigned long long ull;

#define Bsz 256
#define Tn  6000
#define Ln  2000
#define DM  64
#define DI  128
#define NSt 8
#define NBk 2
#define TL  50    // rows per tile in k2
#define CHK 25    // scan chunk length (2 chunks per tile)
#define NCH 80    // chunks per sequence (CHK*NCH == Ln)

// ---------------- scratch (static device allocations) ----------------
__device__ __align__(16) float g_z[2][(size_t)Bsz * Ln * DM];      // residual stream f/b
__device__ __align__(16) float g_xiraw[2][(size_t)Bsz * Ln * DI];  // pre-conv xi (k1 out)
__device__ __align__(16) float g_szg[2][(size_t)Bsz * Ln * DI];    // silu(zg)
__device__ __align__(16) float g_y[2][(size_t)Bsz * Ln * DI];      // scan output y
__device__ __align__(16) float g_dt[2][(size_t)Bsz * Ln * DI];     // cumsum S
__device__ __align__(16) float g_bc[2][(size_t)Bsz * Ln * 16];     // [..|C(8)] only C written
__device__ __align__(16) float g_hf[2][(size_t)Bsz * NCH * DI * NSt];
__device__ __align__(16) float g_hi[2][(size_t)Bsz * NCH * DI * NSt];
__device__ __align__(16) float g_A[2][DI * NSt];
__device__ int g_fast[2][DI];

__device__ __forceinline__ float silu_f(float v) {
    return __fdividef(v, 1.0f + __expf(-v));
}
__device__ __forceinline__ void fma2(ull& d, ull a, ull b) {
    asm("fma.rn.f32x2 %0, %1, %2, %0;" : "+l"(d) : "l"(a), "l"(b));
}
__device__ __forceinline__ float2 up2(ull v) { float2 f; memcpy(&f, &v, 8); return f; }
__device__ __forceinline__ ull pk2(float x, float y) { float2 f = make_float2(x, y); ull v; memcpy(&v, &f, 8); return v; }

// ---------------- k0: front conv (stride 3, VALID) -> zf, zb(reversed) ----
__global__ void k_conv(const float* __restrict__ x, const float* __restrict__ w,
                       const float* __restrict__ cb) {
    size_t idx = (size_t)blockIdx.x * blockDim.x + threadIdx.x;
    if (idx >= (size_t)Bsz * Ln * DM) return;
    int d = (int)(idx & (DM - 1));
    size_t bl = idx >> 6;
    int l = (int)(bl % Ln);
    int b = (int)(bl / Ln);
    const float* xp = x + (size_t)b * Tn + 3 * (size_t)l;
    float v = cb[d] + xp[0] * w[d * 3 + 0] + xp[1] * w[d * 3 + 1] + xp[2] * w[d * 3 + 2];
    g_z[0][bl * DM + d] = v;
    g_z[1][((size_t)b * Ln + (Ln - 1 - l)) * DM + d] = v;
}

// ---------------- k3pre: A = -exp(Alog), fast flag per (c,d) --------------
__global__ void k3pre(int p, const float* __restrict__ f_alog, const float* __restrict__ b_alog) {
    int c = blockIdx.x;
    int d = threadIdx.x;
    const float* alog = (c ? b_alog : f_alog) + ((size_t)p * DI + d) * NSt;
    bool fast = true;
#pragma unroll
    for (int n = 0; n < NSt; n++) {
        float a = -__expf(alog[n]);
        g_A[c][d * NSt + n] = a;
        float tgt = (float)(n + 1);
        if (fabsf(a + tgt) > 1e-5f * tgt) fast = false;
    }
    g_fast[c][d] = fast ? 1 : 0;
}

// ---------------- k1: LN + in_proj (64->256) via f32x2 --------------------
// Weights split into two odd-pitch float planes (conflict-free LDS.32):
//   Wlo[q*65+d] = W[q][d], Whi[q*65+d] = W[q+128][d]
__global__ void __launch_bounds__(256) k1_ln_inproj(int p,
        const float* __restrict__ f_lnw, const float* __restrict__ f_lnb,
        const float* __restrict__ f_inw,
        const float* __restrict__ b_lnw, const float* __restrict__ b_lnb,
        const float* __restrict__ b_inw) {
    extern __shared__ float sm1[];
    float* Wlo = sm1;                  // [128 q][65 pitch]
    float* Whi = sm1 + 128 * 65;       // [128 q][65 pitch]
    float* us  = sm1 + 2 * 128 * 65;   // [64 rows][64 d] float2 dup (u,u)
    int c = blockIdx.y;
    const float* lnw = (c ? b_lnw : f_lnw) + p * DM;
    const float* lnb = (c ? b_lnb : f_lnb) + p * DM;
    const float* inw = (c ? b_inw : f_inw) + (size_t)p * 256 * DM;

    for (int s = threadIdx.x; s < 128 * 64; s += 256) {
        int q = s >> 6, d = s & 63;
        Wlo[q * 65 + d] = inw[q * 64 + d];
        Whi[q * 65 + d] = inw[(q + 128) * 64 + d];
    }

    int warp = threadIdx.x >> 5, lane = threadIdx.x & 31;
    size_t row0 = (size_t)blockIdx.x * 64 + warp * 8;
    const float* zb = g_z[c];
    float lw0 = lnw[lane], lw1 = lnw[lane + 32];
    float lb0 = lnb[lane], lb1 = lnb[lane + 32];
    float* up = us + (size_t)warp * 8 * 64 * 2;

#pragma unroll
    for (int r = 0; r < 8; r++) {
        size_t row = row0 + r;
        float v0 = zb[row * DM + lane], v1 = zb[row * DM + lane + 32];
        float s = v0 + v1, ss = v0 * v0 + v1 * v1;
#pragma unroll
        for (int o = 16; o; o >>= 1) {
            s  += __shfl_xor_sync(0xffffffffu, s, o);
            ss += __shfl_xor_sync(0xffffffffu, ss, o);
        }
        float mean = s * (1.0f / 64.0f);
        float var  = ss * (1.0f / 64.0f) - mean * mean;
        float rstd = rsqrtf(var + 1e-5f);
        float u0 = (v0 - mean) * rstd * lw0 + lb0;
        float u1 = (v1 - mean) * rstd * lw1 + lb1;
        *(float2*)&up[(r * 64 + lane) * 2]      = make_float2(u0, u0);
        *(float2*)&up[(r * 64 + lane + 32) * 2] = make_float2(u1, u1);
    }
    __syncthreads();

    const ull* Up = (const ull*)us + (size_t)warp * 8 * 64;
    const float* L0 = Wlo + (size_t)lane * 65;
    const float* L1 = Wlo + (size_t)(32 + lane) * 65;
    const float* L2 = Wlo + (size_t)(64 + lane) * 65;
    const float* L3 = Wlo + (size_t)(96 + lane) * 65;
    const float* H0 = Whi + (size_t)lane * 65;
    const float* H1 = Whi + (size_t)(32 + lane) * 65;
    const float* H2 = Whi + (size_t)(64 + lane) * 65;
    const float* H3 = Whi + (size_t)(96 + lane) * 65;

    ull acc[4][8];
#pragma unroll
    for (int j = 0; j < 4; j++)
#pragma unroll
        for (int r = 0; r < 8; r++) acc[j][r] = 0ull;

#pragma unroll 2
    for (int d = 0; d < 64; d++) {
        ull w0 = pk2(L0[d], H0[d]);
        ull w1 = pk2(L1[d], H1[d]);
        ull w2 = pk2(L2[d], H2[d]);
        ull w3 = pk2(L3[d], H3[d]);
#pragma unroll
        for (int r = 0; r < 8; r++) {
            ull u = Up[r * 64 + d];
            fma2(acc[0][r], w0, u);
            fma2(acc[1][r], w1, u);
            fma2(acc[2][r], w2, u);
            fma2(acc[3][r], w3, u);
        }
    }

    float* xiraw = g_xiraw[c];
    float* szg = g_szg[c];
#pragma unroll
    for (int j = 0; j < 4; j++) {
        int q = j * 32 + lane;
#pragma unroll
        for (int r = 0; r < 8; r++) {
            float2 v = up2(acc[j][r]);
            xiraw[(row0 + r) * DI + q] = v.x;
            szg[(row0 + r) * DI + q]   = silu_f(v.y);
        }
    }
}

// ---------------- k2f: conv+silu, xp, AND chunk-local scan (dt inline) ----
__global__ void __launch_bounds__(320) k2f(int p,
                              const float* __restrict__ f_cvw, const float* __restrict__ f_cvb,
                              const float* __restrict__ f_xpw, const float* __restrict__ f_dtw,
                              const float* __restrict__ f_dtb, const float* __restrict__ f_Dp,
                              const float* __restrict__ b_cvw, const float* __restrict__ b_cvb,
                              const float* __restrict__ b_xpw, const float* __restrict__ b_dtw,
                              const float* __restrict__ b_dtb, const float* __restrict__ b_Dp) {
    extern __shared__ float sm2[];
    float* xis = sm2;               // [50][132]
    float* bcr = xis + TL * 132;    // [50][20]
    float* xw4 = bcr + TL * 20;     // 2560

    int c = blockIdx.y;
    int tid = threadIdx.x;
    int warp = tid >> 5, lane = tid & 31;
    int d = lane * 4;

    const float* cvwg = (c ? b_cvw : f_cvw) + (size_t)p * DI * 4;
    const float* cvbg = (c ? b_cvb : f_cvb) + p * DI;
    const float* xpwg = (c ? b_xpw : f_xpw) + (size_t)p * 20 * DI;
    const float* dtwg = (c ? b_dtw : f_dtw) + (size_t)p * DI * 4;
    const float* dtbg = (c ? b_dtb : f_dtb) + p * DI;

    for (int s = tid; s < 2560; s += 320) {
        int comp = s & 3, q = s >> 2;
        int eg = q % 5, dd = q / 5;
        xw4[s] = xpwg[(eg * 4 + comp) * DI + dd];
    }

    int chunk = blockIdx.x % (Ln / TL);
    int b = blockIdx.x / (Ln / TL);
    int l0 = chunk * TL;
    const float* xg = g_xiraw[c] + (size_t)b * Ln * DI;

    // ---- conv + silu ----
    {
        float4 r0 = *(const float4*)&cvwg[(d + 0) * 4];
        float4 r1 = *(const float4*)&cvwg[(d + 1) * 4];
        float4 r2 = *(const float4*)&cvwg[(d + 2) * 4];
        float4 r3 = *(const float4*)&cvwg[(d + 3) * 4];
        float4 cw0 = make_float4(r0.x, r1.x, r2.x, r3.x);
        float4 cw1 = make_float4(r0.y, r1.y, r2.y, r3.y);
        float4 cw2 = make_float4(r0.z, r1.z, r2.z, r3.z);
        float4 cw3 = make_float4(r0.w, r1.w, r2.w, r3.w);
        float4 cb4 = *(const float4*)&cvbg[d];
        __syncthreads();   // xw4 staged

        for (int r = warp; r < TL; r += 10) {
            int l = l0 + r;
            float4 z4 = make_float4(0, 0, 0, 0);
            float4 v0 = (l - 3 >= 0) ? *(const float4*)&xg[(size_t)(l - 3) * DI + d] : z4;
            float4 v1 = (l - 2 >= 0) ? *(const float4*)&xg[(size_t)(l - 2) * DI + d] : z4;
            float4 v2 = (l - 1 >= 0) ? *(const float4*)&xg[(size_t)(l - 1) * DI + d] : z4;
            float4 v3 = *(const float4*)&xg[(size_t)l * DI + d];
            float4 a;
            a.x = fmaf(v3.x, cw3.x, fmaf(v2.x, cw2.x, fmaf(v1.x, cw1.x, fmaf(v0.x, cw0.x, cb4.x))));
            a.y = fmaf(v3.y, cw3.y, fmaf(v2.y, cw2.y, fmaf(v1.y, cw1.y, fmaf(v0.y, cw0.y, cb4.y))));
            a.z = fmaf(v3.z, cw3.z, fmaf(v2.z, cw2.z, fmaf(v1.z, cw1.z, fmaf(v0.z, cw0.z, cb4.z))));
            a.w = fmaf(v3.w, cw3.w, fmaf(v2.w, cw2.w, fmaf(v1.w, cw1.w, fmaf(v0.w, cw0.w, cb4.w))));
            a.x = silu_f(a.x); a.y = silu_f(a.y); a.z = silu_f(a.z); a.w = silu_f(a.w);
            *(float4*)&xis[r * 132 + d] = a;
        }
    }
    __syncthreads();

    // ---- xp projection: warp = unit (eg, row-half) ----
    float* bcg = g_bc[c] + (size_t)b * Ln * 16;
    {
        int eg = warp % 5, rh = warp / 5;
        int r = rh * 25 + lane;
        bool act = lane < 25;
        const float4* xr = (const float4*)(xis + (act ? r : 0) * 132);
        ull a01 = 0ull, a23 = 0ull;
#pragma unroll 4
        for (int q = 0; q < 32; q++) {
            float4 x4 = xr[q];
            float xv[4] = {x4.x, x4.y, x4.z, x4.w};
#pragma unroll
            for (int k = 0; k < 4; k++) {
                float4 w4 = *(const float4*)&xw4[((q * 4 + k) * 5 + eg) * 4]; // uniform
                ull xd = pk2(xv[k], xv[k]);
                fma2(a01, xd, pk2(w4.x, w4.y));
                fma2(a23, xd, pk2(w4.z, w4.w));
            }
        }
        if (act) {
            float2 p01 = up2(a01), p23 = up2(a23);
            int e0 = eg * 4;
            *(float4*)&bcr[r * 20 + e0] = make_float4(p01.x, p01.y, p23.x, p23.y);
            if (eg >= 3)
                *(float4*)&bcg[(size_t)(l0 + r) * 16 + (e0 - 4)] =
                    make_float4(p01.x, p01.y, p23.x, p23.y);
        }
    }
    __syncthreads();

    // ---- fused chunk-local scan with inline dt: 256 thr = (chunk, d) ------
    if (tid < 256) {
        int ch = tid >> 7;
        int dd = tid & 127;
        int m = chunk * 2 + ch;
        const float* Dpt = (c ? b_Dp : f_Dp) + p * DI;
        float Dv = Dpt[dd];
        int fast = g_fast[c][dd];
        float4 dw = *(const float4*)&dtwg[dd * 4];
        float db = dtbg[dd];
        float A[NSt];
#pragma unroll
        for (int n = 0; n < NSt; n++) A[n] = g_A[c][dd * NSt + n];

        float h[NSt];
#pragma unroll
        for (int n = 0; n < NSt; n++) h[n] = 0.0f;
        float S = 0.0f;

        size_t gbase = ((size_t)b * Ln + (size_t)(l0 + ch * CHK)) * DI + dd;
        float* Sg = g_dt[c] + gbase;
        float* yg = g_y[c] + gbase;
        int rbase = ch * CHK;

        if (fast) {
            for (int r = 0; r < CHK; r++) {
                int row = rbase + r;
                const float4* bb = (const float4*)(bcr + row * 20);   // warp-uniform
                float4 q4 = bb[0];
                float4 b0 = bb[1], b1 = bb[2], c0 = bb[3], c1 = bb[4];
                float xv = xis[row * 132 + dd];
                float dtv = fmaf(q4.w, dw.w, fmaf(q4.z, dw.z, fmaf(q4.y, dw.y, fmaf(q4.x, dw.x, db))));
                dtv = fmaxf(dtv, 0.0f) + log1pf(__expf(-fabsf(dtv)));
                S += dtv;
                Sg[(size_t)r * DI] = S;
                float Bv[8] = {b0.x, b0.y, b0.z, b0.w, b1.x, b1.y, b1.z, b1.w};
                float Cv[8] = {c0.x, c0.y, c0.z, c0.w, c1.x, c1.y, c1.z, c1.w};
                float dx = dtv * xv;
                float w = __expf(-dtv);
                float e1 = w, e2 = w * w;
                float e3 = e2 * e1, e4 = e2 * e2;
                float e5 = e4 * e1, e6 = e4 * e2, e7 = e4 * e3, e8 = e4 * e4;
                float E[8] = {e1, e2, e3, e4, e5, e6, e7, e8};
                float pr[8];
#pragma unroll
                for (int n = 0; n < NSt; n++) {
                    h[n] = fmaf(h[n], E[n], dx * Bv[n]);
                    pr[n] = h[n] * Cv[n];
                }
                float y = fmaf(xv, Dv, ((pr[0] + pr[1]) + (pr[2] + pr[3])) +
                                       ((pr[4] + pr[5]) + (pr[6] + pr[7])));
                yg[(size_t)r * DI] = y;
            }
        } else {
            for (int r = 0; r < CHK; r++) {
                int row = rbase + r;
                const float4* bb = (const float4*)(bcr + row * 20);
                float4 q4 = bb[0];
                float4 b0 = bb[1], b1 = bb[2], c0 = bb[3], c1 = bb[4];
                float xv = xis[row * 132 + dd];
                float dtv = fmaf(q4.w, dw.w, fmaf(q4.z, dw.z, fmaf(q4.y, dw.y, fmaf(q4.x, dw.x, db))));
                dtv = fmaxf(dtv, 0.0f) + log1pf(__expf(-fabsf(dtv)));
                S += dtv;
                Sg[(size_t)r * DI] = S;
                float Bv[8] = {b0.x, b0.y, b0.z, b0.w, b1.x, b1.y, b1.z, b1.w};
                float Cv[8] = {c0.x, c0.y, c0.z, c0.w, c1.x, c1.y, c1.z, c1.w};
                float dx = dtv * xv;
                float pr[8];
#pragma unroll
                for (int n = 0; n < NSt; n++) {
                    float e = __expf(dtv * A[n]);
                    h[n] = fmaf(h[n], e, dx * Bv[n]);
                    pr[n] = h[n] * Cv[n];
                }
                float y = fmaf(xv, Dv, ((pr[0] + pr[1]) + (pr[2] + pr[3])) +
                                       ((pr[4] + pr[5]) + (pr[6] + pr[7])));
                yg[(size_t)r * DI] = y;
            }
        }

        float4* hfp = (float4*)(g_hf[c] + (((size_t)b * NCH + m) * DI + dd) * NSt);
        hfp[0] = make_float4(h[0], h[1], h[2], h[3]);
        hfp[1] = make_float4(h[4], h[5], h[6], h[7]);
    }
}

// ---------------- k3b: chain chunk states sequentially --------------------
__global__ void k3b_comb() {
    int c = blockIdx.y, b = blockIdx.x, d = threadIdx.x;
    float A[NSt];
#pragma unroll
    for (int n = 0; n < NSt; n++) A[n] = g_A[c][d * NSt + n];
    float hi[NSt];
#pragma unroll
    for (int n = 0; n < NSt; n++) hi[n] = 0.0f;

    for (int m = 0; m < NCH; m++) {
        size_t off = (((size_t)b * NCH + m) * DI + d) * NSt;
        float4* hip = (float4*)(g_hi[c] + off);
        hip[0] = make_float4(hi[0], hi[1], hi[2], hi[3]);
        hip[1] = make_float4(hi[4], hi[5], hi[6], hi[7]);
        float Send = g_dt[c][((size_t)b * Ln + (size_t)m * CHK + CHK - 1) * DI + d];
        const float4* hfp = (const float4*)(g_hf[c] + off);
        float4 f0 = hfp[0], f1 = hfp[1];
        float hf[8] = {f0.x, f0.y, f0.z, f0.w, f1.x, f1.y, f1.z, f1.w};
#pragma unroll
        for (int n = 0; n < NSt; n++) hi[n] = fmaf(__expf(A[n] * Send), hi[n], hf[n]);
    }
}

// ---------------- k4: correction + *silu(zg) + out proj (f32x2) + residual
__global__ void __launch_bounds__(256) k4_outproj(int p, const float* __restrict__ f_ow,
                                                  const float* __restrict__ b_ow) {
    extern __shared__ float sm4[];
    float* ws = sm4;                 // [128 d][66] float2 dup (w,w)
    float* us = sm4 + 128 * 66 * 2;  // [32 rowpairs][128 d] float2 (u_even,u_odd)
    int c = blockIdx.y;
    const float* ow = (c ? b_ow : f_ow) + (size_t)p * DM * DI;

    for (int s = threadIdx.x; s < DM * DI; s += 256) {
        int mm = s >> 7, d = s & 127;
        float v = ow[s];
        int j = mm >> 5, ln = mm & 31;
        *(float2*)&ws[(d * 66 + j * 33 + ln) * 2] = make_float2(v, v);
    }

    size_t row0 = (size_t)blockIdx.x * 64;
    const float* yb  = g_y[c];
    const float* Sb  = g_dt[c];
    const float* sgb = g_szg[c];
    const float* bcb = g_bc[c];
    const float* hib = g_hi[c];

    for (int s = threadIdx.x; s < 64 * 32; s += 256) {
        int r = s >> 5, dq = s & 31;
        int d = dq * 4;
        unsigned int row = (unsigned int)(row0 + r);
        unsigned int b2 = row / Ln;
        unsigned int l  = row % Ln;
        unsigned int m  = l / CHK;
        float4 y4  = *(const float4*)&yb[(size_t)row * DI + d];
        float4 S4  = *(const float4*)&Sb[(size_t)row * DI + d];
        float4 sg4 = *(const float4*)&sgb[(size_t)row * DI + d];
        const float4* C4 = (const float4*)(bcb + (size_t)row * 16 + 8);
        float4 c0 = C4[0], c1 = C4[1];
        float Cv[8] = {c0.x, c0.y, c0.z, c0.w, c1.x, c1.y, c1.z, c1.w};
        float yv[4] = {y4.x, y4.y, y4.z, y4.w};
        float Sv[4] = {S4.x, S4.y, S4.z, S4.w};
        float sv[4] = {sg4.x, sg4.y, sg4.z, sg4.w};
        size_t hbase = ((size_t)b2 * NCH + m) * DI;
#pragma unroll
        for (int q = 0; q < 4; q++) {
            int dd = d + q;
            const float4* H4 = (const float4*)(hib + (hbase + dd) * NSt);
            float4 h0 = H4[0], h1 = H4[1];
            float Hv[8] = {h0.x, h0.y, h0.z, h0.w, h1.x, h1.y, h1.z, h1.w};
            float corr = 0.0f;
            if (g_fast[c][dd]) {
                float e = __expf(-Sv[q]), ep = e;
#pragma unroll
                for (int n = 0; n < NSt; n++) { corr = fmaf(Cv[n] * Hv[n], ep, corr); ep *= e; }
            } else {
#pragma unroll
                for (int n = 0; n < NSt; n++)
                    corr = fmaf(Cv[n] * Hv[n], __expf(g_A[c][dd * NSt + n] * Sv[q]), corr);
            }
            float u = (yv[q] + corr) * sv[q];
            us[(((r >> 1) * DI + dd) * 2) + (r & 1)] = u;
        }
    }
    __syncthreads();

    int warp = threadIdx.x >> 5, lane = threadIdx.x & 31;
    const ull* Wp = (const ull*)ws;
    const ull* Up = (const ull*)us + (size_t)warp * 4 * DI;
    float* zb = g_z[c];
    size_t rw0 = row0 + (size_t)warp * 8;

    ull acc[2][4];
#pragma unroll
    for (int j = 0; j < 2; j++) {
        int mm = j * 32 + lane;
#pragma unroll
        for (int rp = 0; rp < 4; rp++)
            acc[j][rp] = pk2(zb[(rw0 + 2 * rp) * DM + mm], zb[(rw0 + 2 * rp + 1) * DM + mm]);
    }

#pragma unroll 2
    for (int d = 0; d < DI; d++) {
        ull w0 = Wp[d * 66 + lane];
        ull w1 = Wp[d * 66 + 33 + lane];
#pragma unroll
        for (int rp = 0; rp < 4; rp++) {
            ull u = Up[rp * DI + d];
            fma2(acc[0][rp], w0, u);
            fma2(acc[1][rp], w1, u);
        }
    }

#pragma unroll
    for (int j = 0; j < 2; j++) {
        int mm = j * 32 + lane;
#pragma unroll
        for (int rp = 0; rp < 4; rp++) {
            float2 v = up2(acc[j][rp]);
            zb[(rw0 + 2 * rp) * DM + mm]     = v.x;
            zb[(rw0 + 2 * rp + 1) * DM + mm] = v.y;
        }
    }
}

// ---------------- k5: classifier ------------------------------------------
__global__ void k5_cls(const float* __restrict__ cw, const float* __restrict__ cb,
                       float* __restrict__ out) {
    __shared__ float hh[2 * DM];
    int b = blockIdx.x;
    int t = threadIdx.x;
    if (t < DM) hh[t] = g_z[0][((size_t)b * Ln + (Ln - 1)) * DM + t];
    else if (t < 2 * DM) hh[t] = g_z[1][((size_t)b * Ln + (Ln - 1)) * DM + (t - DM)];
    __syncthreads();
    float a = cb[t];
    const float* wr = cw + (size_t)t * 2 * DM;
#pragma unroll 8
    for (int j = 0; j < 2 * DM; j++) a = fmaf(hh[j], wr[j], a);
    out[(size_t)b * 256 + t] = a;
}

// ---------------- launch ---------------------------------------------------
extern "C" void kernel_launch(void* const* d_in, const int* in_sizes, int n_in,
                              void* d_out, int out_size) {
    const float* x      = (const float*)d_in[0];
    const float* conv_w = (const float*)d_in[1];
    const float* conv_b = (const float*)d_in[2];
    const float* F[11];
    const float* Bp[11];
    for (int i = 0; i < 11; i++) {
        F[i]  = (const float*)d_in[3 + i];
        Bp[i] = (const float*)d_in[14 + i];
    }
    const float* cls_w = (const float*)d_in[25];
    const float* cls_b = (const float*)d_in[26];
    float* out = (float*)d_out;

    const int smem1 = (2 * 128 * 65 + 64 * 64 * 2) * 4;
    const int smem2 = (TL * 132 + TL * 20 + 2560) * 4;   // 40640 B
    const int smem4 = (128 * 66 * 2 + 32 * 128 * 2) * 4;
    cudaFuncSetAttribute(k1_ln_inproj, cudaFuncAttributeMaxDynamicSharedMemorySize, smem1);
    cudaFuncSetAttribute(k2f, cudaFuncAttributeMaxDynamicSharedMemorySize, smem2);
    cudaFuncSetAttribute(k4_outproj, cudaFuncAttributeMaxDynamicSharedMemorySize, smem4);

    k_conv<<<(Bsz * Ln * DM + 255) / 256, 256>>>(x, conv_w, conv_b);

    for (int p = 0; p < NBk; p++) {
        k3pre<<<2, DI>>>(p, F[8], Bp[8]);
        k1_ln_inproj<<<dim3(Bsz * Ln / 64, 2), 256, smem1>>>(
            p, F[0], F[1], F[2], Bp[0], Bp[1], Bp[2]);
        k2f<<<dim3(Bsz * (Ln / TL), 2), 320, smem2>>>(
            p, F[3], F[4], F[5], F[6], F[7], F[9],
               Bp[3], Bp[4], Bp[5], Bp[6], Bp[7], Bp[9]);
        k3b_comb<<<dim3(Bsz, 2), DI>>>();
        k4_outproj<<<dim3(Bsz * Ln / 64, 2), 256, smem4>>>(p, F[10], Bp[10]);
    }

    k5_cls<<<Bsz, 256>>>(cls_w, cls_b, out);
}

// round 14
// speedup vs baseline: 1.0814x; 1.0814x over previous
#include <cuda_runtime.h>
#include <string.h>

typedef unsigned long long ull;
typedef unsigned int uint;

#define Bsz 256
#define Tn  6000
#define Ln  2000
#define DM  64
#define DI  128
#define NSt 8
#define NBk 2
#define TL  50
#define CHK 25
#define NCH 80

// ---------------- scratch ----------------
__device__ __align__(16) float g_z[2][(size_t)Bsz * Ln * DM];
__device__ __align__(16) float g_xiraw[2][(size_t)Bsz * Ln * DI];
__device__ __align__(16) float g_szg[2][(size_t)Bsz * Ln * DI];
__device__ __align__(16) float g_y[2][(size_t)Bsz * Ln * DI];
__device__ __align__(16) float g_dt[2][(size_t)Bsz * Ln * DI];
__device__ __align__(16) float g_bc[2][(size_t)Bsz * Ln * 16];
__device__ __align__(16) float g_hf[2][(size_t)Bsz * NCH * DI * NSt];
__device__ __align__(16) float g_hi[2][(size_t)Bsz * NCH * DI * NSt];
__device__ __align__(16) float g_A[2][DI * NSt];
__device__ int g_fast[2][DI];

__device__ __forceinline__ float silu_f(float v) {
    return __fdividef(v, 1.0f + __expf(-v));
}
__device__ __forceinline__ void fma2(ull& d, ull a, ull b) {
    asm("fma.rn.f32x2 %0, %1, %2, %0;" : "+l"(d) : "l"(a), "l"(b));
}
__device__ __forceinline__ float2 up2(ull v) { float2 f; memcpy(&f, &v, 8); return f; }
__device__ __forceinline__ ull pk2(float x, float y) { float2 f = make_float2(x, y); ull v; memcpy(&v, &f, 8); return v; }
__device__ __forceinline__ float tf32f(float x) {
    uint r; asm("cvt.rna.tf32.f32 %0, %1;" : "=r"(r) : "f"(x));
    return __uint_as_float(r);
}
__device__ __forceinline__ void mma_tf32(float* c, uint a0, uint a1, uint a2, uint a3,
                                         uint b0, uint b1) {
    asm volatile("mma.sync.aligned.m16n8k8.row.col.f32.tf32.tf32.f32 "
                 "{%0,%1,%2,%3}, {%4,%5,%6,%7}, {%8,%9}, {%0,%1,%2,%3};"
                 : "+f"(c[0]), "+f"(c[1]), "+f"(c[2]), "+f"(c[3])
                 : "r"(a0), "r"(a1), "r"(a2), "r"(a3), "r"(b0), "r"(b1));
}

// ---------------- k0 ----------------
__global__ void k_conv(const float* __restrict__ x, const float* __restrict__ w,
                       const float* __restrict__ cb) {
    size_t idx = (size_t)blockIdx.x * blockDim.x + threadIdx.x;
    if (idx >= (size_t)Bsz * Ln * DM) return;
    int d = (int)(idx & (DM - 1));
    size_t bl = idx >> 6;
    int l = (int)(bl % Ln);
    int b = (int)(bl / Ln);
    const float* xp = x + (size_t)b * Tn + 3 * (size_t)l;
    float v = cb[d] + xp[0] * w[d * 3 + 0] + xp[1] * w[d * 3 + 1] + xp[2] * w[d * 3 + 2];
    g_z[0][bl * DM + d] = v;
    g_z[1][((size_t)b * Ln + (Ln - 1 - l)) * DM + d] = v;
}

// ---------------- k3pre ----------------
__global__ void k3pre(int p, const float* __restrict__ f_alog, const float* __restrict__ b_alog) {
    int c = blockIdx.x;
    int d = threadIdx.x;
    const float* alog = (c ? b_alog : f_alog) + ((size_t)p * DI + d) * NSt;
    bool fast = true;
#pragma unroll
    for (int n = 0; n < NSt; n++) {
        float a = -__expf(alog[n]);
        g_A[c][d * NSt + n] = a;
        float tgt = (float)(n + 1);
        if (fabsf(a + tgt) > 1e-5f * tgt) fast = false;
    }
    g_fast[c][d] = fast ? 1 : 0;
}

// ---------------- k1: LN + in_proj via tf32 mma.sync ----------------------
// u[64][68] tf32, Wb[256][68] tf32 (B col-major: Wb[q][k]); warp = (m-tile,
// col-half). 128 mma/warp. smem = (64+256)*68*4 = 87040 B.
__global__ void __launch_bounds__(256) k1_ln_inproj(int p,
        const float* __restrict__ f_lnw, const float* __restrict__ f_lnb,
        const float* __restrict__ f_inw,
        const float* __restrict__ b_lnw, const float* __restrict__ b_lnb,
        const float* __restrict__ b_inw) {
    extern __shared__ float sm1[];
    float* us = sm1;             // [64][68]
    float* Wb = sm1 + 64 * 68;   // [256][68]
    int c = blockIdx.y;
    const float* lnw = (c ? b_lnw : f_lnw) + p * DM;
    const float* lnb = (c ? b_lnb : f_lnb) + p * DM;
    const float* inw = (c ? b_inw : f_inw) + (size_t)p * 256 * DM;

    for (int s = threadIdx.x; s < 256 * 64; s += 256) {
        int q = s >> 6, d = s & 63;
        Wb[q * 68 + d] = tf32f(inw[q * 64 + d]);
    }

    int warp = threadIdx.x >> 5, lane = threadIdx.x & 31;
    size_t row0 = (size_t)blockIdx.x * 64;
    const float* zb = g_z[c];
    float lw0 = lnw[lane], lw1 = lnw[lane + 32];
    float lb0 = lnb[lane], lb1 = lnb[lane + 32];

#pragma unroll
    for (int r = 0; r < 8; r++) {
        int rl = warp * 8 + r;
        size_t row = row0 + rl;
        float v0 = zb[row * DM + lane], v1 = zb[row * DM + lane + 32];
        float s = v0 + v1, ss = v0 * v0 + v1 * v1;
#pragma unroll
        for (int o = 16; o; o >>= 1) {
            s  += __shfl_xor_sync(0xffffffffu, s, o);
            ss += __shfl_xor_sync(0xffffffffu, ss, o);
        }
        float mean = s * (1.0f / 64.0f);
        float var  = ss * (1.0f / 64.0f) - mean * mean;
        float rstd = rsqrtf(var + 1e-5f);
        us[rl * 68 + lane]      = tf32f((v0 - mean) * rstd * lw0 + lb0);
        us[rl * 68 + lane + 32] = tf32f((v1 - mean) * rstd * lw1 + lb1);
    }
    __syncthreads();

    int mi = warp & 3;       // m-tile (16 rows each)
    int nh = warp >> 2;      // column half (0: xi, 1: zg)
    int grp = lane >> 2, qd = lane & 3;

    float acc[16][4];
#pragma unroll
    for (int nt = 0; nt < 16; nt++)
#pragma unroll
        for (int j = 0; j < 4; j++) acc[nt][j] = 0.0f;

    const float* Arow = us + mi * 16 * 68;
    const float* Bbase = Wb + (size_t)(nh * 128) * 68;
#pragma unroll
    for (int k = 0; k < 64; k += 8) {
        uint a0 = __float_as_uint(Arow[grp * 68 + k + qd]);
        uint a1 = __float_as_uint(Arow[(grp + 8) * 68 + k + qd]);
        uint a2 = __float_as_uint(Arow[grp * 68 + k + qd + 4]);
        uint a3 = __float_as_uint(Arow[(grp + 8) * 68 + k + qd + 4]);
#pragma unroll
        for (int nt = 0; nt < 16; nt++) {
            const float* bq = Bbase + (size_t)(nt * 8 + grp) * 68 + k + qd;
            uint b0 = __float_as_uint(bq[0]);
            uint b1 = __float_as_uint(bq[4]);
            mma_tf32(acc[nt], a0, a1, a2, a3, b0, b1);
        }
    }

    float* xiraw = g_xiraw[c];
    float* szg = g_szg[c];
#pragma unroll
    for (int nt = 0; nt < 16; nt++) {
        int qc = nt * 8 + 2 * qd;   // column pair within half
#pragma unroll
        for (int half = 0; half < 2; half++) {
            size_t row = row0 + mi * 16 + grp + half * 8;
            float v0 = acc[nt][half * 2 + 0];
            float v1 = acc[nt][half * 2 + 1];
            if (nh == 0) {
                *(float2*)&xiraw[row * DI + qc] = make_float2(v0, v1);
            } else {
                *(float2*)&szg[row * DI + qc] = make_float2(silu_f(v0), silu_f(v1));
            }
        }
    }
}

// ---------------- k2f: conv+silu, xp, chunk-local scan (dt inline) --------
__global__ void __launch_bounds__(320) k2f(int p,
                              const float* __restrict__ f_cvw, const float* __restrict__ f_cvb,
                              const float* __restrict__ f_xpw, const float* __restrict__ f_dtw,
                              const float* __restrict__ f_dtb, const float* __restrict__ f_Dp,
                              const float* __restrict__ b_cvw, const float* __restrict__ b_cvb,
                              const float* __restrict__ b_xpw, const float* __restrict__ b_dtw,
                              const float* __restrict__ b_dtb, const float* __restrict__ b_Dp) {
    extern __shared__ float sm2[];
    float* xis = sm2;               // [50][132]
    float* bcr = xis + TL * 132;    // [50][20]
    float* xw4 = bcr + TL * 20;     // 2560

    int c = blockIdx.y;
    int tid = threadIdx.x;
    int warp = tid >> 5, lane = tid & 31;
    int d = lane * 4;

    const float* cvwg = (c ? b_cvw : f_cvw) + (size_t)p * DI * 4;
    const float* cvbg = (c ? b_cvb : f_cvb) + p * DI;
    const float* xpwg = (c ? b_xpw : f_xpw) + (size_t)p * 20 * DI;
    const float* dtwg = (c ? b_dtw : f_dtw) + (size_t)p * DI * 4;
    const float* dtbg = (c ? b_dtb : f_dtb) + p * DI;

    for (int s = tid; s < 2560; s += 320) {
        int comp = s & 3, q = s >> 2;
        int eg = q % 5, dd = q / 5;
        xw4[s] = xpwg[(eg * 4 + comp) * DI + dd];
    }

    int chunk = blockIdx.x % (Ln / TL);
    int b = blockIdx.x / (Ln / TL);
    int l0 = chunk * TL;
    const float* xg = g_xiraw[c] + (size_t)b * Ln * DI;

    {
        float4 r0 = *(const float4*)&cvwg[(d + 0) * 4];
        float4 r1 = *(const float4*)&cvwg[(d + 1) * 4];
        float4 r2 = *(const float4*)&cvwg[(d + 2) * 4];
        float4 r3 = *(const float4*)&cvwg[(d + 3) * 4];
        float4 cw0 = make_float4(r0.x, r1.x, r2.x, r3.x);
        float4 cw1 = make_float4(r0.y, r1.y, r2.y, r3.y);
        float4 cw2 = make_float4(r0.z, r1.z, r2.z, r3.z);
        float4 cw3 = make_float4(r0.w, r1.w, r2.w, r3.w);
        float4 cb4 = *(const float4*)&cvbg[d];
        __syncthreads();

        for (int r = warp; r < TL; r += 10) {
            int l = l0 + r;
            float4 z4 = make_float4(0, 0, 0, 0);
            float4 v0 = (l - 3 >= 0) ? *(const float4*)&xg[(size_t)(l - 3) * DI + d] : z4;
            float4 v1 = (l - 2 >= 0) ? *(const float4*)&xg[(size_t)(l - 2) * DI + d] : z4;
            float4 v2 = (l - 1 >= 0) ? *(const float4*)&xg[(size_t)(l - 1) * DI + d] : z4;
            float4 v3 = *(const float4*)&xg[(size_t)l * DI + d];
            float4 a;
            a.x = fmaf(v3.x, cw3.x, fmaf(v2.x, cw2.x, fmaf(v1.x, cw1.x, fmaf(v0.x, cw0.x, cb4.x))));
            a.y = fmaf(v3.y, cw3.y, fmaf(v2.y, cw2.y, fmaf(v1.y, cw1.y, fmaf(v0.y, cw0.y, cb4.y))));
            a.z = fmaf(v3.z, cw3.z, fmaf(v2.z, cw2.z, fmaf(v1.z, cw1.z, fmaf(v0.z, cw0.z, cb4.z))));
            a.w = fmaf(v3.w, cw3.w, fmaf(v2.w, cw2.w, fmaf(v1.w, cw1.w, fmaf(v0.w, cw0.w, cb4.w))));
            a.x = silu_f(a.x); a.y = silu_f(a.y); a.z = silu_f(a.z); a.w = silu_f(a.w);
            *(float4*)&xis[r * 132 + d] = a;
        }
    }
    __syncthreads();

    float* bcg = g_bc[c] + (size_t)b * Ln * 16;
    {
        int eg = warp % 5, rh = warp / 5;
        int r = rh * 25 + lane;
        bool act = lane < 25;
        const float4* xr = (const float4*)(xis + (act ? r : 0) * 132);
        ull a01 = 0ull, a23 = 0ull;
#pragma unroll 4
        for (int q = 0; q < 32; q++) {
            float4 x4 = xr[q];
            float xv[4] = {x4.x, x4.y, x4.z, x4.w};
#pragma unroll
            for (int k = 0; k < 4; k++) {
                float4 w4 = *(const float4*)&xw4[((q * 4 + k) * 5 + eg) * 4];
                ull xd = pk2(xv[k], xv[k]);
                fma2(a01, xd, pk2(w4.x, w4.y));
                fma2(a23, xd, pk2(w4.z, w4.w));
            }
        }
        if (act) {
            float2 p01 = up2(a01), p23 = up2(a23);
            int e0 = eg * 4;
            *(float4*)&bcr[r * 20 + e0] = make_float4(p01.x, p01.y, p23.x, p23.y);
            if (eg >= 3)
                *(float4*)&bcg[(size_t)(l0 + r) * 16 + (e0 - 4)] =
                    make_float4(p01.x, p01.y, p23.x, p23.y);
        }
    }
    __syncthreads();

    if (tid < 256) {
        int ch = tid >> 7;
        int dd = tid & 127;
        int m = chunk * 2 + ch;
        const float* Dpt = (c ? b_Dp : f_Dp) + p * DI;
        float Dv = Dpt[dd];
        int fast = g_fast[c][dd];
        float4 dw = *(const float4*)&dtwg[dd * 4];
        float db = dtbg[dd];
        float A[NSt];
#pragma unroll
        for (int n = 0; n < NSt; n++) A[n] = g_A[c][dd * NSt + n];

        float h[NSt];
#pragma unroll
        for (int n = 0; n < NSt; n++) h[n] = 0.0f;
        float S = 0.0f;

        size_t gbase = ((size_t)b * Ln + (size_t)(l0 + ch * CHK)) * DI + dd;
        float* Sg = g_dt[c] + gbase;
        float* yg = g_y[c] + gbase;
        int rbase = ch * CHK;

        if (fast) {
            for (int r = 0; r < CHK; r++) {
                int row = rbase + r;
                const float4* bb = (const float4*)(bcr + row * 20);
                float4 q4 = bb[0];
                float4 b0 = bb[1], b1 = bb[2], c0 = bb[3], c1 = bb[4];
                float xv = xis[row * 132 + dd];
                float dtv = fmaf(q4.w, dw.w, fmaf(q4.z, dw.z, fmaf(q4.y, dw.y, fmaf(q4.x, dw.x, db))));
                dtv = fmaxf(dtv, 0.0f) + log1pf(__expf(-fabsf(dtv)));
                S += dtv;
                Sg[(size_t)r * DI] = S;
                float Bv[8] = {b0.x, b0.y, b0.z, b0.w, b1.x, b1.y, b1.z, b1.w};
                float Cv[8] = {c0.x, c0.y, c0.z, c0.w, c1.x, c1.y, c1.z, c1.w};
                float dx = dtv * xv;
                float w = __expf(-dtv);
                float e1 = w, e2 = w * w;
                float e3 = e2 * e1, e4 = e2 * e2;
                float e5 = e4 * e1, e6 = e4 * e2, e7 = e4 * e3, e8 = e4 * e4;
                float E[8] = {e1, e2, e3, e4, e5, e6, e7, e8};
                float pr[8];
#pragma unroll
                for (int n = 0; n < NSt; n++) {
                    h[n] = fmaf(h[n], E[n], dx * Bv[n]);
                    pr[n] = h[n] * Cv[n];
                }
                float y = fmaf(xv, Dv, ((pr[0] + pr[1]) + (pr[2] + pr[3])) +
                                       ((pr[4] + pr[5]) + (pr[6] + pr[7])));
                yg[(size_t)r * DI] = y;
            }
        } else {
            for (int r = 0; r < CHK; r++) {
                int row = rbase + r;
                const float4* bb = (const float4*)(bcr + row * 20);
                float4 q4 = bb[0];
                float4 b0 = bb[1], b1 = bb[2], c0 = bb[3], c1 = bb[4];
                float xv = xis[row * 132 + dd];
                float dtv = fmaf(q4.w, dw.w, fmaf(q4.z, dw.z, fmaf(q4.y, dw.y, fmaf(q4.x, dw.x, db))));
                dtv = fmaxf(dtv, 0.0f) + log1pf(__expf(-fabsf(dtv)));
                S += dtv;
                Sg[(size_t)r * DI] = S;
                float Bv[8] = {b0.x, b0.y, b0.z, b0.w, b1.x, b1.y, b1.z, b1.w};
                float Cv[8] = {c0.x, c0.y, c0.z, c0.w, c1.x, c1.y, c1.z, c1.w};
                float dx = dtv * xv;
                float pr[8];
#pragma unroll
                for (int n = 0; n < NSt; n++) {
                    float e = __expf(dtv * A[n]);
                    h[n] = fmaf(h[n], e, dx * Bv[n]);
                    pr[n] = h[n] * Cv[n];
                }
                float y = fmaf(xv, Dv, ((pr[0] + pr[1]) + (pr[2] + pr[3])) +
                                       ((pr[4] + pr[5]) + (pr[6] + pr[7])));
                yg[(size_t)r * DI] = y;
            }
        }

        float4* hfp = (float4*)(g_hf[c] + (((size_t)b * NCH + m) * DI + dd) * NSt);
        hfp[0] = make_float4(h[0], h[1], h[2], h[3]);
        hfp[1] = make_float4(h[4], h[5], h[6], h[7]);
    }
}

// ---------------- k3b ----------------
__global__ void k3b_comb() {
    int c = blockIdx.y, b = blockIdx.x, d = threadIdx.x;
    float A[NSt];
#pragma unroll
    for (int n = 0; n < NSt; n++) A[n] = g_A[c][d * NSt + n];
    float hi[NSt];
#pragma unroll
    for (int n = 0; n < NSt; n++) hi[n] = 0.0f;

    for (int m = 0; m < NCH; m++) {
        size_t off = (((size_t)b * NCH + m) * DI + d) * NSt;
        float4* hip = (float4*)(g_hi[c] + off);
        hip[0] = make_float4(hi[0], hi[1], hi[2], hi[3]);
        hip[1] = make_float4(hi[4], hi[5], hi[6], hi[7]);
        float Send = g_dt[c][((size_t)b * Ln + (size_t)m * CHK + CHK - 1) * DI + d];
        const float4* hfp = (const float4*)(g_hf[c] + off);
        float4 f0 = hfp[0], f1 = hfp[1];
        float hf[8] = {f0.x, f0.y, f0.z, f0.w, f1.x, f1.y, f1.z, f1.w};
#pragma unroll
        for (int n = 0; n < NSt; n++) hi[n] = fmaf(__expf(A[n] * Send), hi[n], hf[n]);
    }
}

// ---------------- k4 ----------------
__global__ void __launch_bounds__(256) k4_outproj(int p, const float* __restrict__ f_ow,
                                                  const float* __restrict__ b_ow) {
    extern __shared__ float sm4[];
    float* ws = sm4;                 // [128 d][66] float2 dup (w,w)
    float* us = sm4 + 128 * 66 * 2;  // [32 rowpairs][128 d] float2
    int c = blockIdx.y;
    const float* ow = (c ? b_ow : f_ow) + (size_t)p * DM * DI;

    for (int s = threadIdx.x; s < DM * DI; s += 256) {
        int mm = s >> 7, d = s & 127;
        float v = ow[s];
        int j = mm >> 5, ln = mm & 31;
        *(float2*)&ws[(d * 66 + j * 33 + ln) * 2] = make_float2(v, v);
    }

    size_t row0 = (size_t)blockIdx.x * 64;
    const float* yb  = g_y[c];
    const float* Sb  = g_dt[c];
    const float* sgb = g_szg[c];
    const float* bcb = g_bc[c];
    const float* hib = g_hi[c];

    for (int s = threadIdx.x; s < 64 * 32; s += 256) {
        int r = s >> 5, dq = s & 31;
        int d = dq * 4;
        unsigned int row = (unsigned int)(row0 + r);
        unsigned int b2 = row / Ln;
        unsigned int l  = row % Ln;
        unsigned int m  = l / CHK;
        float4 y4  = *(const float4*)&yb[(size_t)row * DI + d];
        float4 S4  = *(const float4*)&Sb[(size_t)row * DI + d];
        float4 sg4 = *(const float4*)&sgb[(size_t)row * DI + d];
        const float4* C4 = (const float4*)(bcb + (size_t)row * 16 + 8);
        float4 c0 = C4[0], c1 = C4[1];
        float Cv[8] = {c0.x, c0.y, c0.z, c0.w, c1.x, c1.y, c1.z, c1.w};
        float yv[4] = {y4.x, y4.y, y4.z, y4.w};
        float Sv[4] = {S4.x, S4.y, S4.z, S4.w};
        float sv[4] = {sg4.x, sg4.y, sg4.z, sg4.w};
        size_t hbase = ((size_t)b2 * NCH + m) * DI;
#pragma unroll
        for (int q = 0; q < 4; q++) {
            int dd = d + q;
            const float4* H4 = (const float4*)(hib + (hbase + dd) * NSt);
            float4 h0 = H4[0], h1 = H4[1];
            float Hv[8] = {h0.x, h0.y, h0.z, h0.w, h1.x, h1.y, h1.z, h1.w};
            float corr = 0.0f;
            if (g_fast[c][dd]) {
                float e = __expf(-Sv[q]), ep = e;
#pragma unroll
                for (int n = 0; n < NSt; n++) { corr = fmaf(Cv[n] * Hv[n], ep, corr); ep *= e; }
            } else {
#pragma unroll
                for (int n = 0; n < NSt; n++)
                    corr = fmaf(Cv[n] * Hv[n], __expf(g_A[c][dd * NSt + n] * Sv[q]), corr);
            }
            float u = (yv[q] + corr) * sv[q];
            us[(((r >> 1) * DI + dd) * 2) + (r & 1)] = u;
        }
    }
    __syncthreads();

    int warp = threadIdx.x >> 5, lane = threadIdx.x & 31;
    const ull* Wp = (const ull*)ws;
    const ull* Up = (const ull*)us + (size_t)warp * 4 * DI;
    float* zb = g_z[c];
    size_t rw0 = row0 + (size_t)warp * 8;

    ull acc[2][4];
#pragma unroll
    for (int j = 0; j < 2; j++) {
        int mm = j * 32 + lane;
#pragma unroll
        for (int rp = 0; rp < 4; rp++)
            acc[j][rp] = pk2(zb[(rw0 + 2 * rp) * DM + mm], zb[(rw0 + 2 * rp + 1) * DM + mm]);
    }

#pragma unroll 2
    for (int d = 0; d < DI; d++) {
        ull w0 = Wp[d * 66 + lane];
        ull w1 = Wp[d * 66 + 33 + lane];
#pragma unroll
        for (int rp = 0; rp < 4; rp++) {
            ull u = Up[rp * DI + d];
            fma2(acc[0][rp], w0, u);
            fma2(acc[1][rp], w1, u);
        }
    }

#pragma unroll
    for (int j = 0; j < 2; j++) {
        int mm = j * 32 + lane;
#pragma unroll
        for (int rp = 0; rp < 4; rp++) {
            float2 v = up2(acc[j][rp]);
            zb[(rw0 + 2 * rp) * DM + mm]     = v.x;
            zb[(rw0 + 2 * rp + 1) * DM + mm] = v.y;
        }
    }
}

// ---------------- k5 ----------------
__global__ void k5_cls(const float* __restrict__ cw, const float* __restrict__ cb,
                       float* __restrict__ out) {
    __shared__ float hh[2 * DM];
    int b = blockIdx.x;
    int t = threadIdx.x;
    if (t < DM) hh[t] = g_z[0][((size_t)b * Ln + (Ln - 1)) * DM + t];
    else if (t < 2 * DM) hh[t] = g_z[1][((size_t)b * Ln + (Ln - 1)) * DM + (t - DM)];
    __syncthreads();
    float a = cb[t];
    const float* wr = cw + (size_t)t * 2 * DM;
#pragma unroll 8
    for (int j = 0; j < 2 * DM; j++) a = fmaf(hh[j], wr[j], a);
    out[(size_t)b * 256 + t] = a;
}

// ---------------- launch ----------------
extern "C" void kernel_launch(void* const* d_in, const int* in_sizes, int n_in,
                              void* d_out, int out_size) {
    const float* x      = (const float*)d_in[0];
    const float* conv_w = (const float*)d_in[1];
    const float* conv_b = (const float*)d_in[2];
    const float* F[11];
    const float* Bp[11];
    for (int i = 0; i < 11; i++) {
        F[i]  = (const float*)d_in[3 + i];
        Bp[i] = (const float*)d_in[14 + i];
    }
    const float* cls_w = (const float*)d_in[25];
    const float* cls_b = (const float*)d_in[26];
    float* out = (float*)d_out;

    const int smem1 = (64 * 68 + 256 * 68) * 4;          // 87040 B
    const int smem2 = (TL * 132 + TL * 20 + 2560) * 4;   // 40640 B
    const int smem4 = (128 * 66 * 2 + 32 * 128 * 2) * 4;
    cudaFuncSetAttribute(k1_ln_inproj, cudaFuncAttributeMaxDynamicSharedMemorySize, smem1);
    cudaFuncSetAttribute(k2f, cudaFuncAttributeMaxDynamicSharedMemorySize, smem2);
    cudaFuncSetAttribute(k4_outproj, cudaFuncAttributeMaxDynamicSharedMemorySize, smem4);

    k_conv<<<(Bsz * Ln * DM + 255) / 256, 256>>>(x, conv_w, conv_b);

    for (int p = 0; p < NBk; p++) {
        k3pre<<<2, DI>>>(p, F[8], Bp[8]);
        k1_ln_inproj<<<dim3(Bsz * Ln / 64, 2), 256, smem1>>>(
            p, F[0], F[1], F[2], Bp[0], Bp[1], Bp[2]);
        k2f<<<dim3(Bsz * (Ln / TL), 2), 320, smem2>>>(
            p, F[3], F[4], F[5], F[6], F[7], F[9],
               Bp[3], Bp[4], Bp[5], Bp[6], Bp[7], Bp[9]);
        k3b_comb<<<dim3(Bsz, 2), DI>>>();
        k4_outproj<<<dim3(Bsz * Ln / 64, 2), 256, smem4>>>(p, F[10], Bp[10]);
    }

    k5_cls<<<Bsz, 256>>>(cls_w, cls_b, out);
}

// round 15
// speedup vs baseline: 1.2237x; 1.1316x over previous
#include <cuda_runtime.h>
#include <string.h>

typedef unsigned long long ull;
typedef unsigned int uint;

#define Bsz 256
#define Tn  6000
#define Ln  2000
#define DM  64
#define DI  128
#define NSt 8
#define NBk 2
#define TL  50
#define CHK 25
#define NCH 80

// ---------------- scratch ----------------
__device__ __align__(16) float g_z[2][(size_t)Bsz * Ln * DM];
__device__ __align__(16) float g_xiraw[2][(size_t)Bsz * Ln * DI];
__device__ __align__(16) float g_szg[2][(size_t)Bsz * Ln * DI];
__device__ __align__(16) float g_y[2][(size_t)Bsz * Ln * DI];
__device__ __align__(16) float g_dt[2][(size_t)Bsz * Ln * DI];
__device__ __align__(16) float g_bc[2][(size_t)Bsz * Ln * 16];
__device__ __align__(16) float g_hf[2][(size_t)Bsz * NCH * DI * NSt];
__device__ __align__(16) float g_hi[2][(size_t)Bsz * NCH * DI * NSt];
__device__ __align__(16) float g_A[2][DI * NSt];
__device__ int g_fast[2][DI];

__device__ __forceinline__ float silu_f(float v) {
    return __fdividef(v, 1.0f + __expf(-v));
}
__device__ __forceinline__ void fma2(ull& d, ull a, ull b) {
    asm("fma.rn.f32x2 %0, %1, %2, %0;" : "+l"(d) : "l"(a), "l"(b));
}
__device__ __forceinline__ float2 up2(ull v) { float2 f; memcpy(&f, &v, 8); return f; }
__device__ __forceinline__ ull pk2(float x, float y) { float2 f = make_float2(x, y); ull v; memcpy(&v, &f, 8); return v; }
__device__ __forceinline__ float tf32f(float x) {
    uint r; asm("cvt.rna.tf32.f32 %0, %1;" : "=r"(r) : "f"(x));
    return __uint_as_float(r);
}
__device__ __forceinline__ void mma_tf32(float* c, uint a0, uint a1, uint a2, uint a3,
                                         uint b0, uint b1) {
    asm volatile("mma.sync.aligned.m16n8k8.row.col.f32.tf32.tf32.f32 "
                 "{%0,%1,%2,%3}, {%4,%5,%6,%7}, {%8,%9}, {%0,%1,%2,%3};"
                 : "+f"(c[0]), "+f"(c[1]), "+f"(c[2]), "+f"(c[3])
                 : "r"(a0), "r"(a1), "r"(a2), "r"(a3), "r"(b0), "r"(b1));
}

// ---------------- k0 ----------------
__global__ void k_conv(const float* __restrict__ x, const float* __restrict__ w,
                       const float* __restrict__ cb) {
    size_t idx = (size_t)blockIdx.x * blockDim.x + threadIdx.x;
    if (idx >= (size_t)Bsz * Ln * DM) return;
    int d = (int)(idx & (DM - 1));
    size_t bl = idx >> 6;
    int l = (int)(bl % Ln);
    int b = (int)(bl / Ln);
    const float* xp = x + (size_t)b * Tn + 3 * (size_t)l;
    float v = cb[d] + xp[0] * w[d * 3 + 0] + xp[1] * w[d * 3 + 1] + xp[2] * w[d * 3 + 2];
    g_z[0][bl * DM + d] = v;
    g_z[1][((size_t)b * Ln + (Ln - 1 - l)) * DM + d] = v;
}

// ---------------- k3pre ----------------
__global__ void k3pre(int p, const float* __restrict__ f_alog, const float* __restrict__ b_alog) {
    int c = blockIdx.x;
    int d = threadIdx.x;
    const float* alog = (c ? b_alog : f_alog) + ((size_t)p * DI + d) * NSt;
    bool fast = true;
#pragma unroll
    for (int n = 0; n < NSt; n++) {
        float a = -__expf(alog[n]);
        g_A[c][d * NSt + n] = a;
        float tgt = (float)(n + 1);
        if (fabsf(a + tgt) > 1e-5f * tgt) fast = false;
    }
    g_fast[c][d] = fast ? 1 : 0;
}

// ---------------- k1: LN + in_proj via tf32 mma.sync ----------------------
__global__ void __launch_bounds__(256) k1_ln_inproj(int p,
        const float* __restrict__ f_lnw, const float* __restrict__ f_lnb,
        const float* __restrict__ f_inw,
        const float* __restrict__ b_lnw, const float* __restrict__ b_lnb,
        const float* __restrict__ b_inw) {
    extern __shared__ float sm1[];
    float* us = sm1;             // [64][68]
    float* Wb = sm1 + 64 * 68;   // [256][68]
    int c = blockIdx.y;
    const float* lnw = (c ? b_lnw : f_lnw) + p * DM;
    const float* lnb = (c ? b_lnb : f_lnb) + p * DM;
    const float* inw = (c ? b_inw : f_inw) + (size_t)p * 256 * DM;

    for (int s = threadIdx.x; s < 256 * 64; s += 256) {
        int q = s >> 6, d = s & 63;
        Wb[q * 68 + d] = tf32f(inw[q * 64 + d]);
    }

    int warp = threadIdx.x >> 5, lane = threadIdx.x & 31;
    size_t row0 = (size_t)blockIdx.x * 64;
    const float* zb = g_z[c];
    float lw0 = lnw[lane], lw1 = lnw[lane + 32];
    float lb0 = lnb[lane], lb1 = lnb[lane + 32];

#pragma unroll
    for (int r = 0; r < 8; r++) {
        int rl = warp * 8 + r;
        size_t row = row0 + rl;
        float v0 = zb[row * DM + lane], v1 = zb[row * DM + lane + 32];
        float s = v0 + v1, ss = v0 * v0 + v1 * v1;
#pragma unroll
        for (int o = 16; o; o >>= 1) {
            s  += __shfl_xor_sync(0xffffffffu, s, o);
            ss += __shfl_xor_sync(0xffffffffu, ss, o);
        }
        float mean = s * (1.0f / 64.0f);
        float var  = ss * (1.0f / 64.0f) - mean * mean;
        float rstd = rsqrtf(var + 1e-5f);
        us[rl * 68 + lane]      = tf32f((v0 - mean) * rstd * lw0 + lb0);
        us[rl * 68 + lane + 32] = tf32f((v1 - mean) * rstd * lw1 + lb1);
    }
    __syncthreads();

    int mi = warp & 3;
    int nh = warp >> 2;
    int grp = lane >> 2, qd = lane & 3;

    float acc[16][4];
#pragma unroll
    for (int nt = 0; nt < 16; nt++)
#pragma unroll
        for (int j = 0; j < 4; j++) acc[nt][j] = 0.0f;

    const float* Arow = us + mi * 16 * 68;
    const float* Bbase = Wb + (size_t)(nh * 128) * 68;
#pragma unroll
    for (int k = 0; k < 64; k += 8) {
        uint a0 = __float_as_uint(Arow[grp * 68 + k + qd]);
        uint a1 = __float_as_uint(Arow[(grp + 8) * 68 + k + qd]);
        uint a2 = __float_as_uint(Arow[grp * 68 + k + qd + 4]);
        uint a3 = __float_as_uint(Arow[(grp + 8) * 68 + k + qd + 4]);
#pragma unroll
        for (int nt = 0; nt < 16; nt++) {
            const float* bq = Bbase + (size_t)(nt * 8 + grp) * 68 + k + qd;
            uint b0 = __float_as_uint(bq[0]);
            uint b1 = __float_as_uint(bq[4]);
            mma_tf32(acc[nt], a0, a1, a2, a3, b0, b1);
        }
    }

    float* xiraw = g_xiraw[c];
    float* szg = g_szg[c];
#pragma unroll
    for (int nt = 0; nt < 16; nt++) {
        int qc = nt * 8 + 2 * qd;
#pragma unroll
        for (int half = 0; half < 2; half++) {
            size_t row = row0 + mi * 16 + grp + half * 8;
            float v0 = acc[nt][half * 2 + 0];
            float v1 = acc[nt][half * 2 + 1];
            if (nh == 0) {
                *(float2*)&xiraw[row * DI + qc] = make_float2(v0, v1);
            } else {
                *(float2*)&szg[row * DI + qc] = make_float2(silu_f(v0), silu_f(v1));
            }
        }
    }
}

// ---------------- k2f: conv+silu, xp, chunk-local scan (dt inline) --------
__global__ void __launch_bounds__(320) k2f(int p,
                              const float* __restrict__ f_cvw, const float* __restrict__ f_cvb,
                              const float* __restrict__ f_xpw, const float* __restrict__ f_dtw,
                              const float* __restrict__ f_dtb, const float* __restrict__ f_Dp,
                              const float* __restrict__ b_cvw, const float* __restrict__ b_cvb,
                              const float* __restrict__ b_xpw, const float* __restrict__ b_dtw,
                              const float* __restrict__ b_dtb, const float* __restrict__ b_Dp) {
    extern __shared__ float sm2[];
    float* xis = sm2;               // [50][132]
    float* bcr = xis + TL * 132;    // [50][20]
    float* xw4 = bcr + TL * 20;     // 2560

    int c = blockIdx.y;
    int tid = threadIdx.x;
    int warp = tid >> 5, lane = tid & 31;
    int d = lane * 4;

    const float* cvwg = (c ? b_cvw : f_cvw) + (size_t)p * DI * 4;
    const float* cvbg = (c ? b_cvb : f_cvb) + p * DI;
    const float* xpwg = (c ? b_xpw : f_xpw) + (size_t)p * 20 * DI;
    const float* dtwg = (c ? b_dtw : f_dtw) + (size_t)p * DI * 4;
    const float* dtbg = (c ? b_dtb : f_dtb) + p * DI;

    for (int s = tid; s < 2560; s += 320) {
        int comp = s & 3, q = s >> 2;
        int eg = q % 5, dd = q / 5;
        xw4[s] = xpwg[(eg * 4 + comp) * DI + dd];
    }

    int chunk = blockIdx.x % (Ln / TL);
    int b = blockIdx.x / (Ln / TL);
    int l0 = chunk * TL;
    const float* xg = g_xiraw[c] + (size_t)b * Ln * DI;

    {
        float4 r0 = *(const float4*)&cvwg[(d + 0) * 4];
        float4 r1 = *(const float4*)&cvwg[(d + 1) * 4];
        float4 r2 = *(const float4*)&cvwg[(d + 2) * 4];
        float4 r3 = *(const float4*)&cvwg[(d + 3) * 4];
        float4 cw0 = make_float4(r0.x, r1.x, r2.x, r3.x);
        float4 cw1 = make_float4(r0.y, r1.y, r2.y, r3.y);
        float4 cw2 = make_float4(r0.z, r1.z, r2.z, r3.z);
        float4 cw3 = make_float4(r0.w, r1.w, r2.w, r3.w);
        float4 cb4 = *(const float4*)&cvbg[d];
        __syncthreads();

        for (int r = warp; r < TL; r += 10) {
            int l = l0 + r;
            float4 z4 = make_float4(0, 0, 0, 0);
            float4 v0 = (l - 3 >= 0) ? *(const float4*)&xg[(size_t)(l - 3) * DI + d] : z4;
            float4 v1 = (l - 2 >= 0) ? *(const float4*)&xg[(size_t)(l - 2) * DI + d] : z4;
            float4 v2 = (l - 1 >= 0) ? *(const float4*)&xg[(size_t)(l - 1) * DI + d] : z4;
            float4 v3 = *(const float4*)&xg[(size_t)l * DI + d];
            float4 a;
            a.x = fmaf(v3.x, cw3.x, fmaf(v2.x, cw2.x, fmaf(v1.x, cw1.x, fmaf(v0.x, cw0.x, cb4.x))));
            a.y = fmaf(v3.y, cw3.y, fmaf(v2.y, cw2.y, fmaf(v1.y, cw1.y, fmaf(v0.y, cw0.y, cb4.y))));
            a.z = fmaf(v3.z, cw3.z, fmaf(v2.z, cw2.z, fmaf(v1.z, cw1.z, fmaf(v0.z, cw0.z, cb4.z))));
            a.w = fmaf(v3.w, cw3.w, fmaf(v2.w, cw2.w, fmaf(v1.w, cw1.w, fmaf(v0.w, cw0.w, cb4.w))));
            a.x = silu_f(a.x); a.y = silu_f(a.y); a.z = silu_f(a.z); a.w = silu_f(a.w);
            *(float4*)&xis[r * 132 + d] = a;
        }
    }
    __syncthreads();

    float* bcg = g_bc[c] + (size_t)b * Ln * 16;
    {
        int eg = warp % 5, rh = warp / 5;
        int r = rh * 25 + lane;
        bool act = lane < 25;
        const float4* xr = (const float4*)(xis + (act ? r : 0) * 132);
        ull a01 = 0ull, a23 = 0ull;
#pragma unroll 4
        for (int q = 0; q < 32; q++) {
            float4 x4 = xr[q];
            float xv[4] = {x4.x, x4.y, x4.z, x4.w};
#pragma unroll
            for (int k = 0; k < 4; k++) {
                float4 w4 = *(const float4*)&xw4[((q * 4 + k) * 5 + eg) * 4];
                ull xd = pk2(xv[k], xv[k]);
                fma2(a01, xd, pk2(w4.x, w4.y));
                fma2(a23, xd, pk2(w4.z, w4.w));
            }
        }
        if (act) {
            float2 p01 = up2(a01), p23 = up2(a23);
            int e0 = eg * 4;
            *(float4*)&bcr[r * 20 + e0] = make_float4(p01.x, p01.y, p23.x, p23.y);
            if (eg >= 3)
                *(float4*)&bcg[(size_t)(l0 + r) * 16 + (e0 - 4)] =
                    make_float4(p01.x, p01.y, p23.x, p23.y);
        }
    }
    __syncthreads();

    if (tid < 256) {
        int ch = tid >> 7;
        int dd = tid & 127;
        int m = chunk * 2 + ch;
        const float* Dpt = (c ? b_Dp : f_Dp) + p * DI;
        float Dv = Dpt[dd];
        int fast = g_fast[c][dd];
        float4 dw = *(const float4*)&dtwg[dd * 4];
        float db = dtbg[dd];
        float A[NSt];
#pragma unroll
        for (int n = 0; n < NSt; n++) A[n] = g_A[c][dd * NSt + n];

        float h[NSt];
#pragma unroll
        for (int n = 0; n < NSt; n++) h[n] = 0.0f;
        float S = 0.0f;

        size_t gbase = ((size_t)b * Ln + (size_t)(l0 + ch * CHK)) * DI + dd;
        float* Sg = g_dt[c] + gbase;
        float* yg = g_y[c] + gbase;
        int rbase = ch * CHK;

        if (fast) {
            for (int r = 0; r < CHK; r++) {
                int row = rbase + r;
                const float4* bb = (const float4*)(bcr + row * 20);
                float4 q4 = bb[0];
                float4 b0 = bb[1], b1 = bb[2], c0 = bb[3], c1 = bb[4];
                float xv = xis[row * 132 + dd];
                float dtv = fmaf(q4.w, dw.w, fmaf(q4.z, dw.z, fmaf(q4.y, dw.y, fmaf(q4.x, dw.x, db))));
                dtv = fmaxf(dtv, 0.0f) + log1pf(__expf(-fabsf(dtv)));
                S += dtv;
                Sg[(size_t)r * DI] = S;
                float Bv[8] = {b0.x, b0.y, b0.z, b0.w, b1.x, b1.y, b1.z, b1.w};
                float Cv[8] = {c0.x, c0.y, c0.z, c0.w, c1.x, c1.y, c1.z, c1.w};
                float dx = dtv * xv;
                float w = __expf(-dtv);
                float e1 = w, e2 = w * w;
                float e3 = e2 * e1, e4 = e2 * e2;
                float e5 = e4 * e1, e6 = e4 * e2, e7 = e4 * e3, e8 = e4 * e4;
                float E[8] = {e1, e2, e3, e4, e5, e6, e7, e8};
                float pr[8];
#pragma unroll
                for (int n = 0; n < NSt; n++) {
                    h[n] = fmaf(h[n], E[n], dx * Bv[n]);
                    pr[n] = h[n] * Cv[n];
                }
                float y = fmaf(xv, Dv, ((pr[0] + pr[1]) + (pr[2] + pr[3])) +
                                       ((pr[4] + pr[5]) + (pr[6] + pr[7])));
                yg[(size_t)r * DI] = y;
            }
        } else {
            for (int r = 0; r < CHK; r++) {
                int row = rbase + r;
                const float4* bb = (const float4*)(bcr + row * 20);
                float4 q4 = bb[0];
                float4 b0 = bb[1], b1 = bb[2], c0 = bb[3], c1 = bb[4];
                float xv = xis[row * 132 + dd];
                float dtv = fmaf(q4.w, dw.w, fmaf(q4.z, dw.z, fmaf(q4.y, dw.y, fmaf(q4.x, dw.x, db))));
                dtv = fmaxf(dtv, 0.0f) + log1pf(__expf(-fabsf(dtv)));
                S += dtv;
                Sg[(size_t)r * DI] = S;
                float Bv[8] = {b0.x, b0.y, b0.z, b0.w, b1.x, b1.y, b1.z, b1.w};
                float Cv[8] = {c0.x, c0.y, c0.z, c0.w, c1.x, c1.y, c1.z, c1.w};
                float dx = dtv * xv;
                float pr[8];
#pragma unroll
                for (int n = 0; n < NSt; n++) {
                    float e = __expf(dtv * A[n]);
                    h[n] = fmaf(h[n], e, dx * Bv[n]);
                    pr[n] = h[n] * Cv[n];
                }
                float y = fmaf(xv, Dv, ((pr[0] + pr[1]) + (pr[2] + pr[3])) +
                                       ((pr[4] + pr[5]) + (pr[6] + pr[7])));
                yg[(size_t)r * DI] = y;
            }
        }

        float4* hfp = (float4*)(g_hf[c] + (((size_t)b * NCH + m) * DI + dd) * NSt);
        hfp[0] = make_float4(h[0], h[1], h[2], h[3]);
        hfp[1] = make_float4(h[4], h[5], h[6], h[7]);
    }
}

// ---------------- k3b ----------------
__global__ void k3b_comb() {
    int c = blockIdx.y, b = blockIdx.x, d = threadIdx.x;
    float A[NSt];
#pragma unroll
    for (int n = 0; n < NSt; n++) A[n] = g_A[c][d * NSt + n];
    float hi[NSt];
#pragma unroll
    for (int n = 0; n < NSt; n++) hi[n] = 0.0f;

    for (int m = 0; m < NCH; m++) {
        size_t off = (((size_t)b * NCH + m) * DI + d) * NSt;
        float4* hip = (float4*)(g_hi[c] + off);
        hip[0] = make_float4(hi[0], hi[1], hi[2], hi[3]);
        hip[1] = make_float4(hi[4], hi[5], hi[6], hi[7]);
        float Send = g_dt[c][((size_t)b * Ln + (size_t)m * CHK + CHK - 1) * DI + d];
        const float4* hfp = (const float4*)(g_hf[c] + off);
        float4 f0 = hfp[0], f1 = hfp[1];
        float hf[8] = {f0.x, f0.y, f0.z, f0.w, f1.x, f1.y, f1.z, f1.w};
#pragma unroll
        for (int n = 0; n < NSt; n++) hi[n] = fmaf(__expf(A[n] * Send), hi[n], hf[n]);
    }
}

// ---------------- k4: correction + silu(zg) gate + out proj (tf32 mma) ----
// us [64][132] tf32 (A), Wb [64][132] tf32 (B col-major). Residual z added
// fp32 in epilogue. smem = (64+64)*132*4 = 67584 B.
__global__ void __launch_bounds__(256) k4_outproj(int p, const float* __restrict__ f_ow,
                                                  const float* __restrict__ b_ow) {
    extern __shared__ float sm4[];
    float* us = sm4;              // [64][132]
    float* Wb = sm4 + 64 * 132;   // [64 out][132 k]
    int c = blockIdx.y;
    const float* ow = (c ? b_ow : f_ow) + (size_t)p * DM * DI;

    for (int s = threadIdx.x; s < DM * DI; s += 256) {
        int mm = s >> 7, k = s & 127;
        Wb[mm * 132 + k] = tf32f(ow[s]);
    }

    size_t row0 = (size_t)blockIdx.x * 64;
    const float* yb  = g_y[c];
    const float* Sb  = g_dt[c];
    const float* sgb = g_szg[c];
    const float* bcb = g_bc[c];
    const float* hib = g_hi[c];

    for (int s = threadIdx.x; s < 64 * 32; s += 256) {
        int r = s >> 5, dq = s & 31;
        int d = dq * 4;
        unsigned int row = (unsigned int)(row0 + r);
        unsigned int b2 = row / Ln;
        unsigned int l  = row % Ln;
        unsigned int m  = l / CHK;
        float4 y4  = *(const float4*)&yb[(size_t)row * DI + d];
        float4 S4  = *(const float4*)&Sb[(size_t)row * DI + d];
        float4 sg4 = *(const float4*)&sgb[(size_t)row * DI + d];
        const float4* C4 = (const float4*)(bcb + (size_t)row * 16 + 8);
        float4 c0 = C4[0], c1 = C4[1];
        float Cv[8] = {c0.x, c0.y, c0.z, c0.w, c1.x, c1.y, c1.z, c1.w};
        float yv[4] = {y4.x, y4.y, y4.z, y4.w};
        float Sv[4] = {S4.x, S4.y, S4.z, S4.w};
        float sv[4] = {sg4.x, sg4.y, sg4.z, sg4.w};
        size_t hbase = ((size_t)b2 * NCH + m) * DI;
        float u4[4];
#pragma unroll
        for (int q = 0; q < 4; q++) {
            int dd = d + q;
            const float4* H4 = (const float4*)(hib + (hbase + dd) * NSt);
            float4 h0 = H4[0], h1 = H4[1];
            float Hv[8] = {h0.x, h0.y, h0.z, h0.w, h1.x, h1.y, h1.z, h1.w};
            float corr = 0.0f;
            if (g_fast[c][dd]) {
                float e = __expf(-Sv[q]), ep = e;
#pragma unroll
                for (int n = 0; n < NSt; n++) { corr = fmaf(Cv[n] * Hv[n], ep, corr); ep *= e; }
            } else {
#pragma unroll
                for (int n = 0; n < NSt; n++)
                    corr = fmaf(Cv[n] * Hv[n], __expf(g_A[c][dd * NSt + n] * Sv[q]), corr);
            }
            u4[q] = tf32f((yv[q] + corr) * sv[q]);
        }
        *(float4*)&us[r * 132 + d] = make_float4(u4[0], u4[1], u4[2], u4[3]);
    }
    __syncthreads();

    int warp = threadIdx.x >> 5, lane = threadIdx.x & 31;
    int mi = warp & 3;      // 16-row m-tile
    int nh = warp >> 2;     // 32-col half
    int grp = lane >> 2, qd = lane & 3;
    float* zb = g_z[c];

    float acc[4][4];
#pragma unroll
    for (int nt = 0; nt < 4; nt++)
#pragma unroll
        for (int j = 0; j < 4; j++) acc[nt][j] = 0.0f;

    const float* Arow = us + mi * 16 * 132;
#pragma unroll
    for (int k = 0; k < 128; k += 8) {
        uint a0 = __float_as_uint(Arow[grp * 132 + k + qd]);
        uint a1 = __float_as_uint(Arow[(grp + 8) * 132 + k + qd]);
        uint a2 = __float_as_uint(Arow[grp * 132 + k + qd + 4]);
        uint a3 = __float_as_uint(Arow[(grp + 8) * 132 + k + qd + 4]);
#pragma unroll
        for (int nt = 0; nt < 4; nt++) {
            const float* bq = Wb + (size_t)(nh * 32 + nt * 8 + grp) * 132 + k + qd;
            uint b0 = __float_as_uint(bq[0]);
            uint b1 = __float_as_uint(bq[4]);
            mma_tf32(acc[nt], a0, a1, a2, a3, b0, b1);
        }
    }

#pragma unroll
    for (int nt = 0; nt < 4; nt++) {
        int col = nh * 32 + nt * 8 + 2 * qd;
#pragma unroll
        for (int half = 0; half < 2; half++) {
            size_t row = row0 + mi * 16 + grp + half * 8;
            float2 zv = *(float2*)&zb[row * DM + col];
            zv.x += acc[nt][half * 2 + 0];
            zv.y += acc[nt][half * 2 + 1];
            *(float2*)&zb[row * DM + col] = zv;
        }
    }
}

// ---------------- k5 ----------------
__global__ void k5_cls(const float* __restrict__ cw, const float* __restrict__ cb,
                       float* __restrict__ out) {
    __shared__ float hh[2 * DM];
    int b = blockIdx.x;
    int t = threadIdx.x;
    if (t < DM) hh[t] = g_z[0][((size_t)b * Ln + (Ln - 1)) * DM + t];
    else if (t < 2 * DM) hh[t] = g_z[1][((size_t)b * Ln + (Ln - 1)) * DM + (t - DM)];
    __syncthreads();
    float a = cb[t];
    const float* wr = cw + (size_t)t * 2 * DM;
#pragma unroll 8
    for (int j = 0; j < 2 * DM; j++) a = fmaf(hh[j], wr[j], a);
    out[(size_t)b * 256 + t] = a;
}

// ---------------- launch ----------------
extern "C" void kernel_launch(void* const* d_in, const int* in_sizes, int n_in,
                              void* d_out, int out_size) {
    const float* x      = (const float*)d_in[0];
    const float* conv_w = (const float*)d_in[1];
    const float* conv_b = (const float*)d_in[2];
    const float* F[11];
    const float* Bp[11];
    for (int i = 0; i < 11; i++) {
        F[i]  = (const float*)d_in[3 + i];
        Bp[i] = (const float*)d_in[14 + i];
    }
    const float* cls_w = (const float*)d_in[25];
    const float* cls_b = (const float*)d_in[26];
    float* out = (float*)d_out;

    const int smem1 = (64 * 68 + 256 * 68) * 4;          // 87040 B
    const int smem2 = (TL * 132 + TL * 20 + 2560) * 4;   // 40640 B
    const int smem4 = (64 * 132 + 64 * 132) * 4;         // 67584 B
    cudaFuncSetAttribute(k1_ln_inproj, cudaFuncAttributeMaxDynamicSharedMemorySize, smem1);
    cudaFuncSetAttribute(k2f, cudaFuncAttributeMaxDynamicSharedMemorySize, smem2);
    cudaFuncSetAttribute(k4_outproj, cudaFuncAttributeMaxDynamicSharedMemorySize, smem4);

    k_conv<<<(Bsz * Ln * DM + 255) / 256, 256>>>(x, conv_w, conv_b);

    for (int p = 0; p < NBk; p++) {
        k3pre<<<2, DI>>>(p, F[8], Bp[8]);
        k1_ln_inproj<<<dim3(Bsz * Ln / 64, 2), 256, smem1>>>(
            p, F[0], F[1], F[2], Bp[0], Bp[1], Bp[2]);
        k2f<<<dim3(Bsz * (Ln / TL), 2), 320, smem2>>>(
            p, F[3], F[4], F[5], F[6], F[7], F[9],
               Bp[3], Bp[4], Bp[5], Bp[6], Bp[7], Bp[9]);
        k3b_comb<<<dim3(Bsz, 2), DI>>>();
        k4_outproj<<<dim3(Bsz * Ln / 64, 2), 256, smem4>>>(p, F[10], Bp[10]);
    }

    k5_cls<<<Bsz, 256>>>(cls_w, cls_b, out);
}